// round 11
// baseline (speedup 1.0000x reference)
#include <cuda_runtime.h>
#include <cuda_fp16.h>
#include <cstdint>

#define NN 50000
#define EE 800000
#define HF 128    // feature/hidden dim
#define CAP 64    // bucket capacity per node (Poisson(16); P(>64) ~ 1e-20)

// ---- scratch (device globals; no allocation allowed) ----
__device__ __half g_y16[NN * HF];  // messages
__device__ __half g_h16[NN * HF];  // layer-1 output (fp16)
__device__ float  g_dinv[NN];
__device__ int    g_cnt[NN];
__device__ int    g_col[NN * CAP]; // bucket storage

// ---------------- bucket build (single atomic pass) ----------------
__global__ void k_fill_bucket(const int* __restrict__ src,
                              const int* __restrict__ dst, int e) {
    int i = blockIdx.x * blockDim.x + threadIdx.x;
    if (i < e) {
        int d = dst[i];
        int p = atomicAdd(&g_cnt[d], 1);
        if (p < CAP) g_col[d * CAP + p] = src[i];
    }
}

__global__ void k_dinv(int n) {
    int i = blockIdx.x * blockDim.x + threadIdx.x;
    if (i < n) g_dinv[i] = rsqrtf((float)(g_cnt[i] + 1));  // +1 self loop
}

// ---------------- Tensor-core GEMM: Y(fp16) = X @ W [* dinv[row]] ----------------
__device__ __forceinline__ uint32_t sptr(const void* p) {
    return (uint32_t)__cvta_generic_to_shared(p);
}

template <typename T, bool SCALE>
__global__ void __launch_bounds__(256) k_gemm_tc(const T* __restrict__ X,
                                                 const float* __restrict__ W,
                                                 __half* __restrict__ Y, int n) {
    extern __shared__ __half sm[];
    __half (*As)[136] = (__half(*)[136])sm;
    __half (*Bs)[136] = (__half(*)[136])(sm + 128 * 136);
    int t = threadIdx.x;
    int block_row = blockIdx.x * 128;

    // W (fp32) -> Bs (fp16)
    {
        int r0 = t >> 5, c = (t & 31) * 4;
#pragma unroll
        for (int p = 0; p < 16; p++) {
            int r = r0 + p * 8;
            float4 wv = *(const float4*)(W + r * HF + c);
            *(__half2*)&Bs[r][c]     = __floats2half2_rn(wv.x, wv.y);
            *(__half2*)&Bs[r][c + 2] = __floats2half2_rn(wv.z, wv.w);
        }
    }
    // X -> As
    if (sizeof(T) == 4) {
        const float* Xf = (const float*)X;
        int r0 = t >> 5, c = (t & 31) * 4;
#pragma unroll
        for (int p = 0; p < 16; p++) {
            int r = r0 + p * 8;
            int gr = block_row + r;
            float4 xv = make_float4(0.f, 0.f, 0.f, 0.f);
            if (gr < n) xv = *(const float4*)(Xf + (size_t)gr * HF + c);
            *(__half2*)&As[r][c]     = __floats2half2_rn(xv.x, xv.y);
            *(__half2*)&As[r][c + 2] = __floats2half2_rn(xv.z, xv.w);
        }
    } else {
        const __half* Xh = (const __half*)X;
        int r0 = t >> 4, c = (t & 15) * 8;
#pragma unroll
        for (int p = 0; p < 8; p++) {
            int r = r0 + p * 16;
            int gr = block_row + r;
            uint4 xv = make_uint4(0, 0, 0, 0);
            if (gr < n) xv = *(const uint4*)(Xh + (size_t)gr * HF + c);
            *(uint4*)&As[r][c] = xv;
        }
    }
    __syncthreads();

    int lane = t & 31;
    int w = t >> 5;
    int mbase = (w >> 2) * 64;
    int nbase = (w & 3) * 32;

    float acc[4][4][4];
#pragma unroll
    for (int i = 0; i < 4; i++)
#pragma unroll
        for (int j = 0; j < 4; j++)
#pragma unroll
            for (int r = 0; r < 4; r++) acc[i][j][r] = 0.f;

#pragma unroll
    for (int kk = 0; kk < 8; kk++) {
        uint32_t a[4][4];
#pragma unroll
        for (int i = 0; i < 4; i++) {
            int row = mbase + i * 16 + (lane & 7) + ((lane >> 3) & 1) * 8;
            int col = kk * 16 + (lane >> 4) * 8;
            uint32_t ad = sptr(&As[row][col]);
            asm volatile("ldmatrix.sync.aligned.m8n8.x4.shared.b16 {%0,%1,%2,%3}, [%4];"
                         : "=r"(a[i][0]), "=r"(a[i][1]), "=r"(a[i][2]), "=r"(a[i][3])
                         : "r"(ad));
        }
        uint32_t b[4][2];
#pragma unroll
        for (int j = 0; j < 4; j++) {
            int row = kk * 16 + (lane & 15);
            int col = nbase + j * 8;
            uint32_t ad = sptr(&Bs[row][col]);
            asm volatile("ldmatrix.sync.aligned.m8n8.x2.trans.shared.b16 {%0,%1}, [%2];"
                         : "=r"(b[j][0]), "=r"(b[j][1])
                         : "r"(ad));
        }
#pragma unroll
        for (int i = 0; i < 4; i++)
#pragma unroll
            for (int j = 0; j < 4; j++) {
                asm volatile(
                    "mma.sync.aligned.m16n8k16.row.col.f32.f16.f16.f32 "
                    "{%0,%1,%2,%3}, {%4,%5,%6,%7}, {%8,%9}, {%0,%1,%2,%3};"
                    : "+f"(acc[i][j][0]), "+f"(acc[i][j][1]),
                      "+f"(acc[i][j][2]), "+f"(acc[i][j][3])
                    : "r"(a[i][0]), "r"(a[i][1]), "r"(a[i][2]), "r"(a[i][3]),
                      "r"(b[j][0]), "r"(b[j][1]));
            }
    }

    int g = lane >> 2, tg = lane & 3;
#pragma unroll
    for (int i = 0; i < 4; i++) {
        int r0 = block_row + mbase + i * 16 + g;
        float dv0 = 1.f, dv8 = 1.f;
        if (SCALE) {
            if (r0 < n) dv0 = g_dinv[r0];
            if (r0 + 8 < n) dv8 = g_dinv[r0 + 8];
        }
#pragma unroll
        for (int j = 0; j < 4; j++) {
            int c = nbase + j * 8 + tg * 2;
            if (r0 < n)
                *(__half2*)(Y + (size_t)r0 * HF + c) =
                    __floats2half2_rn(acc[i][j][0] * dv0, acc[i][j][1] * dv0);
            if (r0 + 8 < n)
                *(__half2*)(Y + (size_t)(r0 + 8) * HF + c) =
                    __floats2half2_rn(acc[i][j][2] * dv8, acc[i][j][3] * dv8);
        }
    }
}

// ---------------- Pair-per-warp aggregation ----------------
// Half-warp 0 processes even edges, half-warp 1 odd edges. Each lane owns
// 8 features (one uint4 of the fp16 row). Halves combined via shfl_xor(16).
template <bool PRESCALED>
__device__ __forceinline__ void accum8(float* a, uint4 raw, float w) {
    const __half2* h = (const __half2*)&raw;
#pragma unroll
    for (int q = 0; q < 4; q++) {
        float2 f = __half22float2(h[q]);
        if (PRESCALED) { a[2 * q] += f.x; a[2 * q + 1] += f.y; }
        else {
            a[2 * q]     = fmaf(f.x, w, a[2 * q]);
            a[2 * q + 1] = fmaf(f.y, w, a[2 * q + 1]);
        }
    }
}

template <bool PRESCALED>
__device__ __forceinline__ void agg_pair(int node, int sub, int fl,
                                         float dv, float* acc) {
    const uint4* y4 = (const uint4*)g_y16;  // 16 uint4 per row

    // self loop: count once (sub==0 half only)
    if (sub == 0) {
        uint4 raw = __ldg(&y4[(size_t)node * 16 + fl]);
        accum8<PRESCALED>(acc, raw, dv);   // PRESCALED ignores w (plain add)
    }

    const int* bucket = &g_col[node * CAP];
    int len = g_cnt[node];
    if (len > CAP) len = CAP;

    for (int b = 0; b < len; b += 32) {
        int m = len - b; if (m > 32) m = 32;   // warp-uniform
        int   sc = 0;
        float dc = 0.f;
        int lane = sub * 16 + fl;
        if (lane < m) {
            sc = __ldg(&bucket[b + lane]);
            if (!PRESCALED) dc = __ldg(&g_dinv[sc]);
        }
        int pairs = m >> 1;
        int k = 0;
        for (; k + 3 < pairs; k += 4) {        // 4 pairs = 8 edges in flight
            uint4 raw[4]; float dd[4];
#pragma unroll
            for (int u = 0; u < 4; u++) {
                int srcl = 2 * (k + u) + sub;
                int s = __shfl_sync(0xFFFFFFFF, sc, srcl);
                if (!PRESCALED) dd[u] = __shfl_sync(0xFFFFFFFF, dc, srcl);
                raw[u] = __ldg(&y4[(size_t)s * 16 + fl]);
            }
#pragma unroll
            for (int u = 0; u < 4; u++)
                accum8<PRESCALED>(acc, raw[u], dd[u]);
        }
        for (; k < pairs; k++) {
            int srcl = 2 * k + sub;
            int s = __shfl_sync(0xFFFFFFFF, sc, srcl);
            float d = PRESCALED ? 1.f : __shfl_sync(0xFFFFFFFF, dc, srcl);
            uint4 raw = __ldg(&y4[(size_t)s * 16 + fl]);
            accum8<PRESCALED>(acc, raw, d);
        }
        if (m & 1) {   // odd remainder: sub==0 half handles it
            int s = __shfl_sync(0xFFFFFFFF, sc, m - 1);
            float d = PRESCALED ? 1.f : __shfl_sync(0xFFFFFFFF, dc, m - 1);
            uint4 raw = __ldg(&y4[(size_t)s * 16 + fl]);
            if (sub == 0) accum8<PRESCALED>(acc, raw, d);
        }
    }
    // combine even/odd halves: every lane ends with the full sum for its feats
#pragma unroll
    for (int i = 0; i < 8; i++)
        acc[i] += __shfl_xor_sync(0xFFFFFFFF, acc[i], 16);
}

// ---------------- Aggregate (layer 1) -> h (fp16) ----------------
__global__ void __launch_bounds__(256) k_agg(const float* __restrict__ bias, int n) {
    int node = (blockIdx.x * blockDim.x + threadIdx.x) >> 5;
    int lane = threadIdx.x & 31;
    if (node >= n) return;
    int sub = lane >> 4, fl = lane & 15;
    float dv = g_dinv[node];

    float acc[8];
#pragma unroll
    for (int i = 0; i < 8; i++) acc[i] = 0.f;
    agg_pair<false>(node, sub, fl, dv, acc);

    if (sub == 0) {
        float4 b0 = *(const float4*)(bias + 8 * fl);
        float4 b1 = *(const float4*)(bias + 8 * fl + 4);
        float r[8];
        r[0] = fmaxf(fmaf(acc[0], dv, b0.x), 0.f);
        r[1] = fmaxf(fmaf(acc[1], dv, b0.y), 0.f);
        r[2] = fmaxf(fmaf(acc[2], dv, b0.z), 0.f);
        r[3] = fmaxf(fmaf(acc[3], dv, b0.w), 0.f);
        r[4] = fmaxf(fmaf(acc[4], dv, b1.x), 0.f);
        r[5] = fmaxf(fmaf(acc[5], dv, b1.y), 0.f);
        r[6] = fmaxf(fmaf(acc[6], dv, b1.z), 0.f);
        r[7] = fmaxf(fmaf(acc[7], dv, b1.w), 0.f);
        __half2 hp[4];
        hp[0] = __floats2half2_rn(r[0], r[1]);
        hp[1] = __floats2half2_rn(r[2], r[3]);
        hp[2] = __floats2half2_rn(r[4], r[5]);
        hp[3] = __floats2half2_rn(r[6], r[7]);
        ((uint4*)g_h16)[(size_t)node * 16 + fl] = *(const uint4*)hp;
    }
}

// ---------------- Aggregate (layer 2, prescaled y) + final projection ----------------
__global__ void __launch_bounds__(256) k_agg_final(const float* __restrict__ bias,
                                                   const float* __restrict__ Wf,
                                                   const float* __restrict__ bf,
                                                   float* __restrict__ out, int n) {
    int node = (blockIdx.x * blockDim.x + threadIdx.x) >> 5;
    int lane = threadIdx.x & 31;
    if (node >= n) return;
    int sub = lane >> 4, fl = lane & 15;
    float dv = g_dinv[node];

    float acc[8];
#pragma unroll
    for (int i = 0; i < 8; i++) acc[i] = 0.f;
    agg_pair<true>(node, sub, fl, dv, acc);

    float4 b0 = *(const float4*)(bias + 8 * fl);
    float4 b1 = *(const float4*)(bias + 8 * fl + 4);
    float4 w0 = *(const float4*)(Wf + 8 * fl);
    float4 w1 = *(const float4*)(Wf + 8 * fl + 4);
    float p = fmaxf(fmaf(acc[0], dv, b0.x), 0.f) * w0.x
            + fmaxf(fmaf(acc[1], dv, b0.y), 0.f) * w0.y
            + fmaxf(fmaf(acc[2], dv, b0.z), 0.f) * w0.z
            + fmaxf(fmaf(acc[3], dv, b0.w), 0.f) * w0.w
            + fmaxf(fmaf(acc[4], dv, b1.x), 0.f) * w1.x
            + fmaxf(fmaf(acc[5], dv, b1.y), 0.f) * w1.y
            + fmaxf(fmaf(acc[6], dv, b1.z), 0.f) * w1.z
            + fmaxf(fmaf(acc[7], dv, b1.w), 0.f) * w1.w;
    // reduce over the 16 feature-lanes (both halves duplicate; xor<16 stays in half)
#pragma unroll
    for (int off = 8; off > 0; off >>= 1)
        p += __shfl_xor_sync(0xFFFFFFFF, p, off);
    if (lane == 0) out[node] = p + bf[0];
}

// ---------------- launch ----------------
extern "C" void kernel_launch(void* const* d_in, const int* in_sizes, int n_in,
                              void* d_out, int out_size) {
    const float* x  = (const float*)d_in[0];
    const int*   ei = (const int*)d_in[1];
    const float* W1 = (const float*)d_in[2];
    const float* b1 = (const float*)d_in[3];
    const float* W2 = (const float*)d_in[4];
    const float* b2 = (const float*)d_in[5];
    const float* Wf = (const float*)d_in[6];
    const float* bf = (const float*)d_in[7];

    int n = in_sizes[0] / HF;     // 50000
    int e = in_sizes[1] / 2;      // 800000
    const int* src = ei;
    const int* dst = ei + e;

    void* yp; cudaGetSymbolAddress(&yp, g_y16);
    void* hp; cudaGetSymbolAddress(&hp, g_h16);
    void* cp; cudaGetSymbolAddress(&cp, g_cnt);
    __half* Y = (__half*)yp;
    __half* H = (__half*)hp;

    const int SMEM = 2 * 128 * 136 * (int)sizeof(__half);  // 69632

    static cudaStream_t s1 = nullptr;
    static cudaEvent_t ev_fork = nullptr, ev_csr = nullptr;
    if (s1 == nullptr) {
        cudaStreamCreateWithFlags(&s1, cudaStreamNonBlocking);
        cudaEventCreateWithFlags(&ev_fork, cudaEventDisableTiming);
        cudaEventCreateWithFlags(&ev_csr, cudaEventDisableTiming);
        cudaFuncSetAttribute((const void*)k_gemm_tc<float, false>,
                             cudaFuncAttributeMaxDynamicSharedMemorySize, SMEM);
        cudaFuncSetAttribute((const void*)k_gemm_tc<__half, true>,
                             cudaFuncAttributeMaxDynamicSharedMemorySize, SMEM);
    }

    int tb = 256;
    int gemm_blocks = (n + 127) / 128;
    int warp_blocks = (n * 32 + tb - 1) / tb;

    // ---- fork: bucket build on side stream, GEMM1 on main stream ----
    cudaEventRecord(ev_fork, 0);
    cudaStreamWaitEvent(s1, ev_fork, 0);

    cudaMemsetAsync(cp, 0, n * sizeof(int), s1);
    k_fill_bucket<<<(e + tb - 1) / tb, tb, 0, s1>>>(src, dst, e);
    k_dinv<<<(n + tb - 1) / tb, tb, 0, s1>>>(n);
    cudaEventRecord(ev_csr, s1);

    // main stream: layer-1 GEMM (independent of graph structure)
    k_gemm_tc<float, false><<<gemm_blocks, 256, SMEM>>>(x, W1, Y, n);

    // ---- join ----
    cudaStreamWaitEvent(0, ev_csr, 0);

    // Layer 1 aggregation (writes fp16 h)
    k_agg<<<warp_blocks, tb>>>(b1, n);
    // Layer 2 (epilogue prescales by dinv[row])
    k_gemm_tc<__half, true><<<gemm_blocks, 256, SMEM>>>(H, W2, Y, n);
    k_agg_final<<<warp_blocks, tb>>>(b2, Wf, bf, (float*)d_out, n);
}

// round 12
// speedup vs baseline: 1.0896x; 1.0896x over previous
#include <cuda_runtime.h>
#include <cuda_fp16.h>
#include <cstdint>

#define NN 50000
#define EE 800000
#define HF 128    // feature/hidden dim
#define CAP 64    // bucket capacity per node (Poisson(16); P(>64) ~ 1e-20)

// ---- scratch (device globals; no allocation allowed) ----
__device__ __half g_y16[NN * HF];  // messages
__device__ __half g_h16[NN * HF];  // layer-1 output (fp16)
__device__ float  g_dinv[NN];
__device__ int    g_cnt[NN];
__device__ int    g_col[NN * CAP]; // bucket storage

// ---------------- bucket build (single atomic pass) ----------------
__global__ void k_fill_bucket(const int* __restrict__ src,
                              const int* __restrict__ dst, int e) {
    int i = blockIdx.x * blockDim.x + threadIdx.x;
    if (i < e) {
        int d = dst[i];
        int p = atomicAdd(&g_cnt[d], 1);
        if (p < CAP) g_col[d * CAP + p] = src[i];
    }
}

__global__ void k_dinv(int n) {
    int i = blockIdx.x * blockDim.x + threadIdx.x;
    if (i < n) g_dinv[i] = rsqrtf((float)(g_cnt[i] + 1));  // +1 self loop
}

// ---------------- Tensor-core GEMM: Y(fp16) = X @ W [* dinv[row]] ----------------
__device__ __forceinline__ uint32_t sptr(const void* p) {
    return (uint32_t)__cvta_generic_to_shared(p);
}

template <typename T, bool SCALE>
__global__ void __launch_bounds__(256) k_gemm_tc(const T* __restrict__ X,
                                                 const float* __restrict__ W,
                                                 __half* __restrict__ Y, int n) {
    extern __shared__ __half sm[];
    __half (*As)[136] = (__half(*)[136])sm;
    __half (*Bs)[136] = (__half(*)[136])(sm + 128 * 136);
    int t = threadIdx.x;
    int block_row = blockIdx.x * 128;

    // W (fp32) -> Bs (fp16)
    {
        int r0 = t >> 5, c = (t & 31) * 4;
#pragma unroll
        for (int p = 0; p < 16; p++) {
            int r = r0 + p * 8;
            float4 wv = *(const float4*)(W + r * HF + c);
            *(__half2*)&Bs[r][c]     = __floats2half2_rn(wv.x, wv.y);
            *(__half2*)&Bs[r][c + 2] = __floats2half2_rn(wv.z, wv.w);
        }
    }
    // X -> As
    if (sizeof(T) == 4) {
        const float* Xf = (const float*)X;
        int r0 = t >> 5, c = (t & 31) * 4;
#pragma unroll
        for (int p = 0; p < 16; p++) {
            int r = r0 + p * 8;
            int gr = block_row + r;
            float4 xv = make_float4(0.f, 0.f, 0.f, 0.f);
            if (gr < n) xv = *(const float4*)(Xf + (size_t)gr * HF + c);
            *(__half2*)&As[r][c]     = __floats2half2_rn(xv.x, xv.y);
            *(__half2*)&As[r][c + 2] = __floats2half2_rn(xv.z, xv.w);
        }
    } else {
        const __half* Xh = (const __half*)X;
        int r0 = t >> 4, c = (t & 15) * 8;
#pragma unroll
        for (int p = 0; p < 8; p++) {
            int r = r0 + p * 16;
            int gr = block_row + r;
            uint4 xv = make_uint4(0, 0, 0, 0);
            if (gr < n) xv = *(const uint4*)(Xh + (size_t)gr * HF + c);
            *(uint4*)&As[r][c] = xv;
        }
    }
    __syncthreads();

    int lane = t & 31;
    int w = t >> 5;
    int mbase = (w >> 2) * 64;
    int nbase = (w & 3) * 32;

    float acc[4][4][4];
#pragma unroll
    for (int i = 0; i < 4; i++)
#pragma unroll
        for (int j = 0; j < 4; j++)
#pragma unroll
            for (int r = 0; r < 4; r++) acc[i][j][r] = 0.f;

#pragma unroll
    for (int kk = 0; kk < 8; kk++) {
        uint32_t a[4][4];
#pragma unroll
        for (int i = 0; i < 4; i++) {
            int row = mbase + i * 16 + (lane & 7) + ((lane >> 3) & 1) * 8;
            int col = kk * 16 + (lane >> 4) * 8;
            uint32_t ad = sptr(&As[row][col]);
            asm volatile("ldmatrix.sync.aligned.m8n8.x4.shared.b16 {%0,%1,%2,%3}, [%4];"
                         : "=r"(a[i][0]), "=r"(a[i][1]), "=r"(a[i][2]), "=r"(a[i][3])
                         : "r"(ad));
        }
        uint32_t b[4][2];
#pragma unroll
        for (int j = 0; j < 4; j++) {
            int row = kk * 16 + (lane & 15);
            int col = nbase + j * 8;
            uint32_t ad = sptr(&Bs[row][col]);
            asm volatile("ldmatrix.sync.aligned.m8n8.x2.trans.shared.b16 {%0,%1}, [%2];"
                         : "=r"(b[j][0]), "=r"(b[j][1])
                         : "r"(ad));
        }
#pragma unroll
        for (int i = 0; i < 4; i++)
#pragma unroll
            for (int j = 0; j < 4; j++) {
                asm volatile(
                    "mma.sync.aligned.m16n8k16.row.col.f32.f16.f16.f32 "
                    "{%0,%1,%2,%3}, {%4,%5,%6,%7}, {%8,%9}, {%0,%1,%2,%3};"
                    : "+f"(acc[i][j][0]), "+f"(acc[i][j][1]),
                      "+f"(acc[i][j][2]), "+f"(acc[i][j][3])
                    : "r"(a[i][0]), "r"(a[i][1]), "r"(a[i][2]), "r"(a[i][3]),
                      "r"(b[j][0]), "r"(b[j][1]));
            }
    }

    int g = lane >> 2, tg = lane & 3;
#pragma unroll
    for (int i = 0; i < 4; i++) {
        int r0 = block_row + mbase + i * 16 + g;
        float dv0 = 1.f, dv8 = 1.f;
        if (SCALE) {
            if (r0 < n) dv0 = g_dinv[r0];
            if (r0 + 8 < n) dv8 = g_dinv[r0 + 8];
        }
#pragma unroll
        for (int j = 0; j < 4; j++) {
            int c = nbase + j * 8 + tg * 2;
            if (r0 < n)
                *(__half2*)(Y + (size_t)r0 * HF + c) =
                    __floats2half2_rn(acc[i][j][0] * dv0, acc[i][j][1] * dv0);
            if (r0 + 8 < n)
                *(__half2*)(Y + (size_t)(r0 + 8) * HF + c) =
                    __floats2half2_rn(acc[i][j][2] * dv8, acc[i][j][3] * dv8);
        }
    }
}

// gather one fp16 row fragment (4 feats) as float4
__device__ __forceinline__ float4 ld_row4(const uint2* __restrict__ y2,
                                          int node, int lane) {
    uint2 raw = __ldg(&y2[(size_t)node * 32 + lane]);
    __half2 a = *reinterpret_cast<const __half2*>(&raw.x);
    __half2 b = *reinterpret_cast<const __half2*>(&raw.y);
    float2 f0 = __half22float2(a);
    float2 f1 = __half22float2(b);
    return make_float4(f0.x, f0.y, f1.x, f1.y);
}

__device__ __forceinline__ void acc_fma(float4& acc, const float4 v, float d) {
    acc.x = fmaf(v.x, d, acc.x); acc.y = fmaf(v.y, d, acc.y);
    acc.z = fmaf(v.z, d, acc.z); acc.w = fmaf(v.w, d, acc.w);
}
__device__ __forceinline__ void acc_add(float4& acc, const float4 v) {
    acc.x += v.x; acc.y += v.y; acc.z += v.z; acc.w += v.w;
}

// Batched agg body (R8 structure, unroll 8 for MLP).
// PRESCALED: y rows carry dinv[src].
template <bool PRESCALED>
__device__ __forceinline__ float4 agg_body(int node, int lane, float dv) {
    const uint2* y2 = (const uint2*)g_y16;
    float4 self = ld_row4(y2, node, lane);
    float4 acc;
    if (PRESCALED) acc = self;
    else acc = make_float4(self.x * dv, self.y * dv, self.z * dv, self.w * dv);

    const int* bucket = &g_col[node * CAP];
    int len = g_cnt[node];
    if (len > CAP) len = CAP;

    for (int b = 0; b < len; b += 32) {
        int m = len - b; if (m > 32) m = 32;   // warp-uniform
        int   sc = 0;
        float dc = 0.f;
        if (lane < m) {
            sc = __ldg(&bucket[b + lane]);     // coalesced batch of indices
            if (!PRESCALED) dc = __ldg(&g_dinv[sc]);
        }
        int kk = 0;
        for (; kk + 7 < m; kk += 8) {          // 8 gathers in flight
            int s[8];
            uint2 raw[8];
#pragma unroll
            for (int u = 0; u < 8; u++)
                s[u] = __shfl_sync(0xFFFFFFFF, sc, kk + u);
#pragma unroll
            for (int u = 0; u < 8; u++)
                raw[u] = __ldg(&y2[(size_t)s[u] * 32 + lane]);
#pragma unroll
            for (int u = 0; u < 8; u++) {
                __half2 h0 = *reinterpret_cast<const __half2*>(&raw[u].x);
                __half2 h1 = *reinterpret_cast<const __half2*>(&raw[u].y);
                float2 f0 = __half22float2(h0);
                float2 f1 = __half22float2(h1);
                float4 v = make_float4(f0.x, f0.y, f1.x, f1.y);
                if (PRESCALED) acc_add(acc, v);
                else {
                    float d = __shfl_sync(0xFFFFFFFF, dc, kk + u);
                    acc_fma(acc, v, d);
                }
            }
        }
        for (; kk + 3 < m; kk += 4) {
            int s0 = __shfl_sync(0xFFFFFFFF, sc, kk);
            int s1 = __shfl_sync(0xFFFFFFFF, sc, kk + 1);
            int s2 = __shfl_sync(0xFFFFFFFF, sc, kk + 2);
            int s3 = __shfl_sync(0xFFFFFFFF, sc, kk + 3);
            float4 v0 = ld_row4(y2, s0, lane);
            float4 v1 = ld_row4(y2, s1, lane);
            float4 v2 = ld_row4(y2, s2, lane);
            float4 v3 = ld_row4(y2, s3, lane);
            if (PRESCALED) {
                acc_add(acc, v0); acc_add(acc, v1);
                acc_add(acc, v2); acc_add(acc, v3);
            } else {
                float d0 = __shfl_sync(0xFFFFFFFF, dc, kk);
                float d1 = __shfl_sync(0xFFFFFFFF, dc, kk + 1);
                float d2 = __shfl_sync(0xFFFFFFFF, dc, kk + 2);
                float d3 = __shfl_sync(0xFFFFFFFF, dc, kk + 3);
                acc_fma(acc, v0, d0); acc_fma(acc, v1, d1);
                acc_fma(acc, v2, d2); acc_fma(acc, v3, d3);
            }
        }
        for (; kk < m; kk++) {
            int s0 = __shfl_sync(0xFFFFFFFF, sc, kk);
            float4 v0 = ld_row4(y2, s0, lane);
            if (PRESCALED) acc_add(acc, v0);
            else {
                float d0 = __shfl_sync(0xFFFFFFFF, dc, kk);
                acc_fma(acc, v0, d0);
            }
        }
    }
    return acc;
}

// ---------------- Aggregate (layer 1) -> h (fp16) ----------------
__global__ void __launch_bounds__(128) k_agg(const float* __restrict__ bias, int n) {
    int node = (blockIdx.x * blockDim.x + threadIdx.x) >> 5;
    int lane = threadIdx.x & 31;
    if (node >= n) return;
    float dv = g_dinv[node];
    float4 acc = agg_body<false>(node, lane, dv);
    float4 b = *(const float4*)(bias + lane * 4);
    __half2 p0 = __floats2half2_rn(fmaxf(fmaf(acc.x, dv, b.x), 0.f),
                                   fmaxf(fmaf(acc.y, dv, b.y), 0.f));
    __half2 p1 = __floats2half2_rn(fmaxf(fmaf(acc.z, dv, b.z), 0.f),
                                   fmaxf(fmaf(acc.w, dv, b.w), 0.f));
    uint2 pk;
    pk.x = *reinterpret_cast<uint32_t*>(&p0);
    pk.y = *reinterpret_cast<uint32_t*>(&p1);
    ((uint2*)g_h16)[(size_t)node * 32 + lane] = pk;
}

// ---------------- Aggregate (layer 2, prescaled y) + final projection ----------------
__global__ void __launch_bounds__(128) k_agg_final(const float* __restrict__ bias,
                                                   const float* __restrict__ Wf,
                                                   const float* __restrict__ bf,
                                                   float* __restrict__ out, int n) {
    int node = (blockIdx.x * blockDim.x + threadIdx.x) >> 5;
    int lane = threadIdx.x & 31;
    if (node >= n) return;
    float dv = g_dinv[node];
    float4 acc = agg_body<true>(node, lane, dv);
    float4 b = *(const float4*)(bias + lane * 4);
    float4 w = ((const float4*)Wf)[lane];
    float p = fmaxf(fmaf(acc.x, dv, b.x), 0.f) * w.x
            + fmaxf(fmaf(acc.y, dv, b.y), 0.f) * w.y
            + fmaxf(fmaf(acc.z, dv, b.z), 0.f) * w.z
            + fmaxf(fmaf(acc.w, dv, b.w), 0.f) * w.w;
#pragma unroll
    for (int off = 16; off > 0; off >>= 1)
        p += __shfl_xor_sync(0xFFFFFFFF, p, off);
    if (lane == 0) out[node] = p + bf[0];
}

// ---------------- launch ----------------
extern "C" void kernel_launch(void* const* d_in, const int* in_sizes, int n_in,
                              void* d_out, int out_size) {
    const float* x  = (const float*)d_in[0];
    const int*   ei = (const int*)d_in[1];
    const float* W1 = (const float*)d_in[2];
    const float* b1 = (const float*)d_in[3];
    const float* W2 = (const float*)d_in[4];
    const float* b2 = (const float*)d_in[5];
    const float* Wf = (const float*)d_in[6];
    const float* bf = (const float*)d_in[7];

    int n = in_sizes[0] / HF;     // 50000
    int e = in_sizes[1] / 2;      // 800000
    const int* src = ei;
    const int* dst = ei + e;

    void* yp; cudaGetSymbolAddress(&yp, g_y16);
    void* hp; cudaGetSymbolAddress(&hp, g_h16);
    void* cp; cudaGetSymbolAddress(&cp, g_cnt);
    __half* Y = (__half*)yp;
    __half* H = (__half*)hp;

    const int SMEM = 2 * 128 * 136 * (int)sizeof(__half);  // 69632

    static cudaStream_t s1 = nullptr;
    static cudaEvent_t ev_fork = nullptr, ev_csr = nullptr;
    if (s1 == nullptr) {
        cudaStreamCreateWithFlags(&s1, cudaStreamNonBlocking);
        cudaEventCreateWithFlags(&ev_fork, cudaEventDisableTiming);
        cudaEventCreateWithFlags(&ev_csr, cudaEventDisableTiming);
        cudaFuncSetAttribute((const void*)k_gemm_tc<float, false>,
                             cudaFuncAttributeMaxDynamicSharedMemorySize, SMEM);
        cudaFuncSetAttribute((const void*)k_gemm_tc<__half, true>,
                             cudaFuncAttributeMaxDynamicSharedMemorySize, SMEM);
    }

    int tb = 256;
    int atb = 128;   // agg block size (finer scheduling granularity)
    int gemm_blocks = (n + 127) / 128;
    int agg_blocks = (n * 32 + atb - 1) / atb;

    // ---- fork: bucket build on side stream, GEMM1 on main stream ----
    cudaEventRecord(ev_fork, 0);
    cudaStreamWaitEvent(s1, ev_fork, 0);

    cudaMemsetAsync(cp, 0, n * sizeof(int), s1);
    k_fill_bucket<<<(e + tb - 1) / tb, tb, 0, s1>>>(src, dst, e);
    k_dinv<<<(n + tb - 1) / tb, tb, 0, s1>>>(n);
    cudaEventRecord(ev_csr, s1);

    // main stream: layer-1 GEMM (independent of graph structure)
    k_gemm_tc<float, false><<<gemm_blocks, 256, SMEM>>>(x, W1, Y, n);

    // ---- join ----
    cudaStreamWaitEvent(0, ev_csr, 0);

    // Layer 1 aggregation (writes fp16 h)
    k_agg<<<agg_blocks, atb>>>(b1, n);
    // Layer 2 (epilogue prescales by dinv[row])
    k_gemm_tc<__half, true><<<gemm_blocks, 256, SMEM>>>(H, W2, Y, n);
    k_agg_final<<<agg_blocks, atb>>>(b2, Wf, bf, (float*)d_out, n);
}

// round 13
// speedup vs baseline: 1.0947x; 1.0047x over previous
#include <cuda_runtime.h>
#include <cuda_fp16.h>
#include <cstdint>

#define NN 50000
#define EE 800000
#define HF 128    // feature/hidden dim
#define CAP 64    // bucket capacity per node (Poisson(16); P(>64) ~ 1e-20)

// ---- scratch (device globals; no allocation allowed) ----
__device__ __half g_y16[NN * HF];          // messages (prescaled by dinv[src])
__device__ __half g_h16[NN * HF];          // layer-1 output (fp16)
__device__ float  g_dinv[NN];
__device__ int    g_cnt[NN];
__device__ unsigned short g_col[NN * CAP]; // bucket storage (node ids < 65536)

// ---------------- bucket build (single atomic pass) ----------------
__global__ void k_fill_bucket(const int* __restrict__ src,
                              const int* __restrict__ dst, int e) {
    int i = blockIdx.x * blockDim.x + threadIdx.x;
    if (i < e) {
        int d = dst[i];
        int p = atomicAdd(&g_cnt[d], 1);
        if (p < CAP) g_col[d * CAP + p] = (unsigned short)src[i];
    }
}

__global__ void k_dinv(int n) {
    int i = blockIdx.x * blockDim.x + threadIdx.x;
    if (i < n) g_dinv[i] = rsqrtf((float)(g_cnt[i] + 1));  // +1 self loop
}

// ---------------- scale pass: y[row] *= dinv[row] (layer-1 messages) ----------------
__global__ void __launch_bounds__(256) k_scale_y(int n) {
    int i = blockIdx.x * blockDim.x + threadIdx.x;  // one uint4 (8 halves)
    if (i >= n * 16) return;
    int row = i >> 4;
    __half2 dv2 = __float2half2_rn(g_dinv[row]);
    uint4* p = (uint4*)g_y16;
    uint4 v = p[i];
    __half2* h = (__half2*)&v;
    h[0] = __hmul2(h[0], dv2);
    h[1] = __hmul2(h[1], dv2);
    h[2] = __hmul2(h[2], dv2);
    h[3] = __hmul2(h[3], dv2);
    p[i] = v;
}

// ---------------- Tensor-core GEMM: Y(fp16) = X @ W [* dinv[row]] ----------------
__device__ __forceinline__ uint32_t sptr(const void* p) {
    return (uint32_t)__cvta_generic_to_shared(p);
}

template <typename T, bool SCALE>
__global__ void __launch_bounds__(256) k_gemm_tc(const T* __restrict__ X,
                                                 const float* __restrict__ W,
                                                 __half* __restrict__ Y, int n) {
    extern __shared__ __half sm[];
    __half (*As)[136] = (__half(*)[136])sm;
    __half (*Bs)[136] = (__half(*)[136])(sm + 128 * 136);
    int t = threadIdx.x;
    int block_row = blockIdx.x * 128;

    // W (fp32) -> Bs (fp16)
    {
        int r0 = t >> 5, c = (t & 31) * 4;
#pragma unroll
        for (int p = 0; p < 16; p++) {
            int r = r0 + p * 8;
            float4 wv = *(const float4*)(W + r * HF + c);
            *(__half2*)&Bs[r][c]     = __floats2half2_rn(wv.x, wv.y);
            *(__half2*)&Bs[r][c + 2] = __floats2half2_rn(wv.z, wv.w);
        }
    }
    // X -> As
    if (sizeof(T) == 4) {
        const float* Xf = (const float*)X;
        int r0 = t >> 5, c = (t & 31) * 4;
#pragma unroll
        for (int p = 0; p < 16; p++) {
            int r = r0 + p * 8;
            int gr = block_row + r;
            float4 xv = make_float4(0.f, 0.f, 0.f, 0.f);
            if (gr < n) xv = *(const float4*)(Xf + (size_t)gr * HF + c);
            *(__half2*)&As[r][c]     = __floats2half2_rn(xv.x, xv.y);
            *(__half2*)&As[r][c + 2] = __floats2half2_rn(xv.z, xv.w);
        }
    } else {
        const __half* Xh = (const __half*)X;
        int r0 = t >> 4, c = (t & 15) * 8;
#pragma unroll
        for (int p = 0; p < 8; p++) {
            int r = r0 + p * 16;
            int gr = block_row + r;
            uint4 xv = make_uint4(0, 0, 0, 0);
            if (gr < n) xv = *(const uint4*)(Xh + (size_t)gr * HF + c);
            *(uint4*)&As[r][c] = xv;
        }
    }
    __syncthreads();

    int lane = t & 31;
    int w = t >> 5;
    int mbase = (w >> 2) * 64;
    int nbase = (w & 3) * 32;

    float acc[4][4][4];
#pragma unroll
    for (int i = 0; i < 4; i++)
#pragma unroll
        for (int j = 0; j < 4; j++)
#pragma unroll
            for (int r = 0; r < 4; r++) acc[i][j][r] = 0.f;

#pragma unroll
    for (int kk = 0; kk < 8; kk++) {
        uint32_t a[4][4];
#pragma unroll
        for (int i = 0; i < 4; i++) {
            int row = mbase + i * 16 + (lane & 7) + ((lane >> 3) & 1) * 8;
            int col = kk * 16 + (lane >> 4) * 8;
            uint32_t ad = sptr(&As[row][col]);
            asm volatile("ldmatrix.sync.aligned.m8n8.x4.shared.b16 {%0,%1,%2,%3}, [%4];"
                         : "=r"(a[i][0]), "=r"(a[i][1]), "=r"(a[i][2]), "=r"(a[i][3])
                         : "r"(ad));
        }
        uint32_t b[4][2];
#pragma unroll
        for (int j = 0; j < 4; j++) {
            int row = kk * 16 + (lane & 15);
            int col = nbase + j * 8;
            uint32_t ad = sptr(&Bs[row][col]);
            asm volatile("ldmatrix.sync.aligned.m8n8.x2.trans.shared.b16 {%0,%1}, [%2];"
                         : "=r"(b[j][0]), "=r"(b[j][1])
                         : "r"(ad));
        }
#pragma unroll
        for (int i = 0; i < 4; i++)
#pragma unroll
            for (int j = 0; j < 4; j++) {
                asm volatile(
                    "mma.sync.aligned.m16n8k16.row.col.f32.f16.f16.f32 "
                    "{%0,%1,%2,%3}, {%4,%5,%6,%7}, {%8,%9}, {%0,%1,%2,%3};"
                    : "+f"(acc[i][j][0]), "+f"(acc[i][j][1]),
                      "+f"(acc[i][j][2]), "+f"(acc[i][j][3])
                    : "r"(a[i][0]), "r"(a[i][1]), "r"(a[i][2]), "r"(a[i][3]),
                      "r"(b[j][0]), "r"(b[j][1]));
            }
    }

    int g = lane >> 2, tg = lane & 3;
#pragma unroll
    for (int i = 0; i < 4; i++) {
        int r0 = block_row + mbase + i * 16 + g;
        float dv0 = 1.f, dv8 = 1.f;
        if (SCALE) {
            if (r0 < n) dv0 = g_dinv[r0];
            if (r0 + 8 < n) dv8 = g_dinv[r0 + 8];
        }
#pragma unroll
        for (int j = 0; j < 4; j++) {
            int c = nbase + j * 8 + tg * 2;
            if (r0 < n)
                *(__half2*)(Y + (size_t)r0 * HF + c) =
                    __floats2half2_rn(acc[i][j][0] * dv0, acc[i][j][1] * dv0);
            if (r0 + 8 < n)
                *(__half2*)(Y + (size_t)(r0 + 8) * HF + c) =
                    __floats2half2_rn(acc[i][j][2] * dv8, acc[i][j][3] * dv8);
        }
    }
}

// ---------------- packed f32x2 helpers (Blackwell FADD2 path) ----------------
__device__ __forceinline__ unsigned long long h2f2(uint32_t h) {
    unsigned long long r;
    asm("{\n\t"
        ".reg .b16 l, h;\n\t"
        ".reg .f32 lo, hi;\n\t"
        "mov.b32 {l, h}, %1;\n\t"
        "cvt.f32.f16 lo, l;\n\t"
        "cvt.f32.f16 hi, h;\n\t"
        "mov.b64 %0, {lo, hi};\n\t"
        "}" : "=l"(r) : "r"(h));
    return r;
}
__device__ __forceinline__ void add2(unsigned long long& a, unsigned long long v) {
    asm("add.rn.f32x2 %0, %0, %1;" : "+l"(a) : "l"(v));
}
__device__ __forceinline__ float2 unpack2(unsigned long long a) {
    float2 f;
    asm("mov.b64 {%0, %1}, %2;" : "=f"(f.x), "=f"(f.y) : "l"(a));
    return f;
}

// ---------------- Aggregation body: sum of prescaled rows ----------------
// acc = y[node] + sum_s y[s]  (all rows already carry dinv[src])
__device__ __forceinline__ float4 agg_sum(int node, int lane) {
    const uint2* y2 = (const uint2*)g_y16;
    uint2 self = __ldg(&y2[(size_t)node * 32 + lane]);
    unsigned long long a0 = h2f2(self.x);
    unsigned long long a1 = h2f2(self.y);

    const unsigned short* bucket = &g_col[node * CAP];
    int len = g_cnt[node];
    if (len > CAP) len = CAP;

    for (int b = 0; b < len; b += 32) {
        int m = len - b; if (m > 32) m = 32;   // warp-uniform
        int sc = 0;
        if (lane < m) sc = __ldg(&bucket[b + lane]);
        int kk = 0;
        for (; kk + 7 < m; kk += 8) {          // 8 gathers in flight
            uint2 raw[8];
#pragma unroll
            for (int u = 0; u < 8; u++) {
                int s = __shfl_sync(0xFFFFFFFF, sc, kk + u);
                raw[u] = __ldg(&y2[(size_t)s * 32 + lane]);
            }
#pragma unroll
            for (int u = 0; u < 8; u++) {
                add2(a0, h2f2(raw[u].x));
                add2(a1, h2f2(raw[u].y));
            }
        }
        for (; kk < m; kk++) {
            int s = __shfl_sync(0xFFFFFFFF, sc, kk);
            uint2 raw = __ldg(&y2[(size_t)s * 32 + lane]);
            add2(a0, h2f2(raw.x));
            add2(a1, h2f2(raw.y));
        }
    }
    float2 f0 = unpack2(a0);
    float2 f1 = unpack2(a1);
    return make_float4(f0.x, f0.y, f1.x, f1.y);
}

// ---------------- Aggregate (layer 1) -> h (fp16) ----------------
__global__ void __launch_bounds__(128) k_agg(const float* __restrict__ bias, int n) {
    int node = (blockIdx.x * blockDim.x + threadIdx.x) >> 5;
    int lane = threadIdx.x & 31;
    if (node >= n) return;
    float dv = g_dinv[node];
    float4 acc = agg_sum(node, lane);
    float4 b = *(const float4*)(bias + lane * 4);
    __half2 p0 = __floats2half2_rn(fmaxf(fmaf(acc.x, dv, b.x), 0.f),
                                   fmaxf(fmaf(acc.y, dv, b.y), 0.f));
    __half2 p1 = __floats2half2_rn(fmaxf(fmaf(acc.z, dv, b.z), 0.f),
                                   fmaxf(fmaf(acc.w, dv, b.w), 0.f));
    uint2 pk;
    pk.x = *reinterpret_cast<uint32_t*>(&p0);
    pk.y = *reinterpret_cast<uint32_t*>(&p1);
    ((uint2*)g_h16)[(size_t)node * 32 + lane] = pk;
}

// ---------------- Aggregate (layer 2) + final projection ----------------
__global__ void __launch_bounds__(128) k_agg_final(const float* __restrict__ bias,
                                                   const float* __restrict__ Wf,
                                                   const float* __restrict__ bf,
                                                   float* __restrict__ out, int n) {
    int node = (blockIdx.x * blockDim.x + threadIdx.x) >> 5;
    int lane = threadIdx.x & 31;
    if (node >= n) return;
    float dv = g_dinv[node];
    float4 acc = agg_sum(node, lane);
    float4 b = *(const float4*)(bias + lane * 4);
    float4 w = ((const float4*)Wf)[lane];
    float p = fmaxf(fmaf(acc.x, dv, b.x), 0.f) * w.x
            + fmaxf(fmaf(acc.y, dv, b.y), 0.f) * w.y
            + fmaxf(fmaf(acc.z, dv, b.z), 0.f) * w.z
            + fmaxf(fmaf(acc.w, dv, b.w), 0.f) * w.w;
#pragma unroll
    for (int off = 16; off > 0; off >>= 1)
        p += __shfl_xor_sync(0xFFFFFFFF, p, off);
    if (lane == 0) out[node] = p + bf[0];
}

// ---------------- launch ----------------
extern "C" void kernel_launch(void* const* d_in, const int* in_sizes, int n_in,
                              void* d_out, int out_size) {
    const float* x  = (const float*)d_in[0];
    const int*   ei = (const int*)d_in[1];
    const float* W1 = (const float*)d_in[2];
    const float* b1 = (const float*)d_in[3];
    const float* W2 = (const float*)d_in[4];
    const float* b2 = (const float*)d_in[5];
    const float* Wf = (const float*)d_in[6];
    const float* bf = (const float*)d_in[7];

    int n = in_sizes[0] / HF;     // 50000
    int e = in_sizes[1] / 2;      // 800000
    const int* src = ei;
    const int* dst = ei + e;

    void* yp; cudaGetSymbolAddress(&yp, g_y16);
    void* hp; cudaGetSymbolAddress(&hp, g_h16);
    void* cp; cudaGetSymbolAddress(&cp, g_cnt);
    __half* Y = (__half*)yp;
    __half* H = (__half*)hp;

    const int SMEM = 2 * 128 * 136 * (int)sizeof(__half);  // 69632

    static cudaStream_t s1 = nullptr;
    static cudaEvent_t ev_fork = nullptr, ev_csr = nullptr;
    if (s1 == nullptr) {
        cudaStreamCreateWithFlags(&s1, cudaStreamNonBlocking);
        cudaEventCreateWithFlags(&ev_fork, cudaEventDisableTiming);
        cudaEventCreateWithFlags(&ev_csr, cudaEventDisableTiming);
        cudaFuncSetAttribute((const void*)k_gemm_tc<float, false>,
                             cudaFuncAttributeMaxDynamicSharedMemorySize, SMEM);
        cudaFuncSetAttribute((const void*)k_gemm_tc<__half, true>,
                             cudaFuncAttributeMaxDynamicSharedMemorySize, SMEM);
    }

    int tb = 256;
    int atb = 128;
    int gemm_blocks = (n + 127) / 128;
    int agg_blocks = (n * 32 + atb - 1) / atb;

    // ---- fork: bucket build on side stream, GEMM1 on main stream ----
    cudaEventRecord(ev_fork, 0);
    cudaStreamWaitEvent(s1, ev_fork, 0);

    cudaMemsetAsync(cp, 0, n * sizeof(int), s1);
    k_fill_bucket<<<(e + tb - 1) / tb, tb, 0, s1>>>(src, dst, e);
    k_dinv<<<(n + tb - 1) / tb, tb, 0, s1>>>(n);
    cudaEventRecord(ev_csr, s1);

    // main stream: layer-1 GEMM (independent of graph structure)
    k_gemm_tc<float, false><<<gemm_blocks, 256, SMEM>>>(x, W1, Y, n);

    // ---- join ----
    cudaStreamWaitEvent(0, ev_csr, 0);

    // prescale layer-1 messages by dinv[src], then aggregate
    k_scale_y<<<(n * 16 + tb - 1) / tb, tb>>>(n);
    k_agg<<<agg_blocks, atb>>>(b1, n);
    // Layer 2 (epilogue prescales by dinv[row])
    k_gemm_tc<__half, true><<<gemm_blocks, 256, SMEM>>>(H, W2, Y, n);
    k_agg_final<<<agg_blocks, atb>>>(b2, Wf, bf, (float*)d_out, n);
}